// round 3
// baseline (speedup 1.0000x reference)
#include <cuda_runtime.h>
#include <math.h>

#define FULLMASK 0xffffffffu
#define Bn   64
#define Wn   128
#define Fn   132
#define An   128
#define TGTn 3
#define En   8
#define HIDn 16
#define OUTn 128
#define NROW (Bn*Wn)

// ---------------- scratch (device globals; no allocation) ----------------
__device__ float g_Lo[NROW*En];
__device__ float g_Ro[NROW*En];
__device__ float g_hL[NROW*HIDn];
__device__ float g_hR[NROW*HIDn];
__device__ float g_bn[2][2][HIDn];
__device__ float g_xw0[NROW*48];
__device__ float g_h1fin[Bn*HIDn];

__device__ __forceinline__ float sigm_(float x) { return 1.0f / (1.0f + __expf(-x)); }
__device__ __forceinline__ float tanh_(float x) { return fmaf(2.0f, sigm_(2.0f * x), -1.0f); }

// ============================================================================
// K1: gate GRU (2 layers, H=8) + softmax. One warp per (side,batch).
// Lane g<24 owns gate-row g (rows 0-7=r, 8-15=z, 16-23=n). h replicated.
// ============================================================================
__global__ void __launch_bounds__(32) k_gate(
    const float* __restrict__ Local, const float* __restrict__ Remote,
    const float* __restrict__ Wih0, const float* __restrict__ Whh0,
    const float* __restrict__ bih0, const float* __restrict__ bhh0,
    const float* __restrict__ Wih1, const float* __restrict__ Whh1,
    const float* __restrict__ bih1, const float* __restrict__ bhh1)
{
    const int lane = threadIdx.x;
    const int side = blockIdx.x >> 6;
    const int b    = blockIdx.x & 63;
    const float* in  = side ? Remote : Local;
    float*       out = side ? g_Ro   : g_Lo;

    float wa=0.f, wb=0.f, wc=0.f, bi0=0.f, bh0=0.f, bi1=0.f, bh1=0.f;
    float u0[8], wi1[8], u1[8];
#pragma unroll
    for (int k = 0; k < 8; k++) { u0[k]=0.f; wi1[k]=0.f; u1[k]=0.f; }
    if (lane < 24) {
        wa = Wih0[lane*3+0]; wb = Wih0[lane*3+1]; wc = Wih0[lane*3+2];
        bi0 = bih0[lane]; bh0 = bhh0[lane];
        bi1 = bih1[lane]; bh1 = bhh1[lane];
#pragma unroll
        for (int k = 0; k < 8; k++) {
            u0[k]  = Whh0[lane*8+k];
            wi1[k] = Wih1[lane*8+k];
            u1[k]  = Whh1[lane*8+k];
        }
    }

    float h0[8], h1[8];
#pragma unroll
    for (int j = 0; j < 8; j++) { h0[j]=0.f; h1[j]=0.f; }

    const float* px = in + (size_t)b * Wn * Fn + An;
    float x0 = px[0], x1 = px[1], x2 = px[2];

    for (int t = 0; t < Wn; t++) {
        float cx0 = x0, cx1 = x1, cx2 = x2;
        if (t + 1 < Wn) {
            const float* pn = px + (size_t)(t + 1) * Fn;
            x0 = pn[0]; x1 = pn[1]; x2 = pn[2];
        }
        // layer 0
        float xw = fmaf(wa, cx0, fmaf(wb, cx1, fmaf(wc, cx2, bi0)));
        float gh = bh0;
#pragma unroll
        for (int k = 0; k < 8; k++) gh = fmaf(u0[k], h0[k], gh);
        float s  = sigm_(xw + gh);
        float r  = __shfl_sync(FULLMASK, s, lane & 7);
        float nv = tanh_(fmaf(r, gh, xw));
#pragma unroll
        for (int j = 0; j < 8; j++) {
            float z = __shfl_sync(FULLMASK, s,  8 + j);
            float n = __shfl_sync(FULLMASK, nv, 16 + j);
            h0[j] = fmaf(z, h0[j] - n, n);
        }
        // layer 1
        float xw1 = bi1;
#pragma unroll
        for (int k = 0; k < 8; k++) xw1 = fmaf(wi1[k], h0[k], xw1);
        float gh1 = bh1;
#pragma unroll
        for (int k = 0; k < 8; k++) gh1 = fmaf(u1[k], h1[k], gh1);
        float s1  = sigm_(xw1 + gh1);
        float r1  = __shfl_sync(FULLMASK, s1, lane & 7);
        float nv1 = tanh_(fmaf(r1, gh1, xw1));
#pragma unroll
        for (int j = 0; j < 8; j++) {
            float z = __shfl_sync(FULLMASK, s1,  8 + j);
            float n = __shfl_sync(FULLMASK, nv1, 16 + j);
            h1[j] = fmaf(z, h1[j] - n, n);
        }
        // softmax over replicated h1[0..7]
        float m = h1[0];
#pragma unroll
        for (int j = 1; j < 8; j++) m = fmaxf(m, h1[j]);
        float ex[8], ssum = 0.f;
#pragma unroll
        for (int j = 0; j < 8; j++) { ex[j] = __expf(h1[j] - m); ssum += ex[j]; }
        float inv = __frcp_rn(ssum);
        if (lane < 8) {
            float v = ex[0];
#pragma unroll
            for (int j = 1; j < 8; j++) if (lane == j) v = ex[j];
            out[((size_t)b * Wn + t) * En + lane] = v * inv;
        }
    }
}

// ============================================================================
// K2: expert layer-1: h[n,h] = sum_e om[n,e] * (x[n]·w1[e,:,h] + b1[e,h])
// ============================================================================
#define K2_SMEM_BYTES ((16384 + 128*129 + 1024 + 128) * 4)
__global__ void k_exp1(
    const float* __restrict__ Local, const float* __restrict__ Remote,
    const float* __restrict__ w1, const float* __restrict__ b1)
{
    extern __shared__ float sm[];
    float* sw1 = sm;
    float* sx  = sw1 + 16384;
    float* som = sx + 128 * 129;
    float* sb1 = som + 1024;

    const int tid  = threadIdx.x;
    const int side = blockIdx.x >> 6;
    const int rb   = blockIdx.x & 63;
    const int n0   = rb * 128;
    const float* in  = side ? Remote : Local;
    const float* om  = side ? g_Ro   : g_Lo;
    float*       dst = side ? g_hR   : g_hL;

    {
        const float4* w14 = (const float4*)w1;
        float4* sw14 = (float4*)sw1;
        for (int i = tid; i < 4096; i += 256) sw14[i] = w14[i];
        for (int i = tid; i < 128 * 128; i += 256) {
            int r = i >> 7, c = i & 127;
            sx[r * 129 + c] = in[(size_t)(n0 + r) * Fn + c];
        }
        for (int i = tid; i < 1024; i += 256) som[i] = om[(size_t)n0 * En + i];
        if (tid < 128) sb1[tid] = b1[tid];
    }
    __syncthreads();

    const int r     = tid >> 1;
    const int hbase = (tid & 1) * 8;
    const float* xrow = sx + r * 129;

    float acc[8];
#pragma unroll
    for (int j = 0; j < 8; j++) acc[j] = 0.f;

    for (int e = 0; e < 8; e++) {
        float pe[8];
#pragma unroll
        for (int j = 0; j < 8; j++) pe[j] = sb1[e * 16 + hbase + j];
        const float* wp = sw1 + e * 2048 + hbase;
#pragma unroll 4
        for (int i = 0; i < 128; i++) {
            float xv = xrow[i];
            float4 wA = *(const float4*)(wp + i * 16);
            float4 wB = *(const float4*)(wp + i * 16 + 4);
            pe[0] = fmaf(xv, wA.x, pe[0]); pe[1] = fmaf(xv, wA.y, pe[1]);
            pe[2] = fmaf(xv, wA.z, pe[2]); pe[3] = fmaf(xv, wA.w, pe[3]);
            pe[4] = fmaf(xv, wB.x, pe[4]); pe[5] = fmaf(xv, wB.y, pe[5]);
            pe[6] = fmaf(xv, wB.z, pe[6]); pe[7] = fmaf(xv, wB.w, pe[7]);
        }
        float oe = som[r * 8 + e];
#pragma unroll
        for (int j = 0; j < 8; j++) acc[j] = fmaf(oe, pe[j], acc[j]);
    }
    float* op = dst + (size_t)(n0 + r) * 16 + hbase;
    ((float4*)op)[0] = make_float4(acc[0], acc[1], acc[2], acc[3]);
    ((float4*)op)[1] = make_float4(acc[4], acc[5], acc[6], acc[7]);
}

// ============================================================================
// K2b: deterministic BN statistics. 32 blocks = (side,h), 256 threads.
// ============================================================================
__global__ void k_bnstat()
{
    __shared__ float ss[256], sq[256];
    const int side = blockIdx.x >> 4, h = blockIdx.x & 15, tid = threadIdx.x;
    const float* src = side ? g_hR : g_hL;
    float s = 0.f, q = 0.f;
    for (int r = tid; r < NROW; r += 256) {
        float v = src[(size_t)r * 16 + h];
        s += v; q = fmaf(v, v, q);
    }
    ss[tid] = s; sq[tid] = q;
    __syncthreads();
    for (int ofs = 128; ofs > 0; ofs >>= 1) {
        if (tid < ofs) { ss[tid] += ss[tid + ofs]; sq[tid] += sq[tid + ofs]; }
        __syncthreads();
    }
    if (tid == 0) { g_bn[side][0][h] = ss[0]; g_bn[side][1][h] = sq[0]; }
}

// ============================================================================
// K3: BN+elu, expert layer-2, Z=ZL+ZR, mixer layer-0 input projection.
// ============================================================================
__global__ void k_exp2(
    const float* __restrict__ w2, const float* __restrict__ b2,
    const float* __restrict__ aeg, const float* __restrict__ aebt,
    const float* __restrict__ Wih0m, const float* __restrict__ bih0m)
{
    __shared__ float sw2[2048], sb2[128], sW[768], sbi[48], sg[16], sbt[16];
    __shared__ float sstat[2][2][16];
    const int tid = threadIdx.x;
    for (int i = tid; i < 2048; i += 64) sw2[i] = w2[i];
    for (int i = tid; i < 768;  i += 64) sW[i]  = Wih0m[i];
    for (int i = tid; i < 128;  i += 64) sb2[i] = b2[i];
    if (tid < 48)  sbi[tid] = bih0m[tid];
    if (tid < 16)  { sg[tid] = aeg[tid]; sbt[tid] = aebt[tid]; }
    if (tid < 32) {
        int side = tid >> 4, h = tid & 15;
        float mean = g_bn[side][0][h] * (1.0f / NROW);
        float var  = g_bn[side][1][h] * (1.0f / NROW) - mean * mean;
        sstat[side][0][h] = mean;
        sstat[side][1][h] = rsqrtf(var + 1e-5f);
    }
    __syncthreads();

    const int n = blockIdx.x * 64 + tid;
    float z[16];
#pragma unroll
    for (int o = 0; o < 16; o++) z[o] = 0.f;

#pragma unroll 1
    for (int side = 0; side < 2; side++) {
        const float* hsrc = side ? g_hR : g_hL;
        const float* osrc = side ? g_Ro : g_Lo;
        float hv[16];
        const float4* hp = (const float4*)(hsrc + (size_t)n * 16);
#pragma unroll
        for (int q4 = 0; q4 < 4; q4++) {
            float4 v = hp[q4];
            hv[q4*4+0]=v.x; hv[q4*4+1]=v.y; hv[q4*4+2]=v.z; hv[q4*4+3]=v.w;
        }
        float omv[8];
#pragma unroll
        for (int e = 0; e < 8; e++) omv[e] = osrc[(size_t)n * 8 + e];
#pragma unroll
        for (int h = 0; h < 16; h++) {
            float v = fmaf(sg[h] * (hv[h] - sstat[side][0][h]), sstat[side][1][h], sbt[h]);
            hv[h] = (v > 0.f) ? v : expm1f(v);
        }
#pragma unroll 1
        for (int e = 0; e < 8; e++) {
            float pe[16];
#pragma unroll
            for (int o = 0; o < 16; o++) pe[o] = sb2[e * 16 + o];
#pragma unroll
            for (int h = 0; h < 16; h++) {
                float hvv = hv[h];
                const float* wrow = sw2 + e * 256 + h * 16;
#pragma unroll
                for (int o = 0; o < 16; o++) pe[o] = fmaf(hvv, wrow[o], pe[o]);
            }
            float oe = omv[e];
#pragma unroll
            for (int o = 0; o < 16; o++) z[o] = fmaf(oe, pe[o], z[o]);
        }
    }

    float* dst = g_xw0 + (size_t)n * 48;
#pragma unroll 1
    for (int g0 = 0; g0 < 48; g0 += 4) {
        float tmp[4];
#pragma unroll
        for (int q = 0; q < 4; q++) {
            float a = sbi[g0 + q];
#pragma unroll
            for (int k = 0; k < 16; k++) a = fmaf(z[k], sW[(g0 + q) * 16 + k], a);
            tmp[q] = a;
        }
        *(float4*)(dst + g0) = make_float4(tmp[0], tmp[1], tmp[2], tmp[3]);
    }
}

// ============================================================================
// K4: mixer GRU (2 layers, H=16), one warp per batch.
// Lane l owns gate rows l (r/z) and 32+l (n, l<16). h in lanes 0..15.
// ============================================================================
__global__ void __launch_bounds__(32) k_mixer(
    const float* __restrict__ Whh0, const float* __restrict__ bhh0,
    const float* __restrict__ Wih1, const float* __restrict__ bih1,
    const float* __restrict__ Whh1, const float* __restrict__ bhh1)
{
    const int lane = threadIdx.x;
    const int b    = blockIdx.x;
    const bool hasB = (lane < 16);
    const int gA = lane, gB = 32 + lane;

    float uA0[16], uB0[16], wiA[16], wiB[16], uA1[16], uB1[16];
#pragma unroll
    for (int k = 0; k < 16; k++) {
        uA0[k] = Whh0[gA * 16 + k];
        wiA[k] = Wih1[gA * 16 + k];
        uA1[k] = Whh1[gA * 16 + k];
        uB0[k] = hasB ? Whh0[gB * 16 + k] : 0.f;
        wiB[k] = hasB ? Wih1[gB * 16 + k] : 0.f;
        uB1[k] = hasB ? Whh1[gB * 16 + k] : 0.f;
    }
    float bhA0 = bhh0[gA], bhB0 = hasB ? bhh0[gB] : 0.f;
    float biA1 = bih1[gA], biB1 = hasB ? bih1[gB] : 0.f;
    float bhA1 = bhh1[gA], bhB1 = hasB ? bhh1[gB] : 0.f;

    float h0 = 0.f, h1 = 0.f;
    const float* xp = g_xw0 + (size_t)b * Wn * 48;
    float xA = xp[lane];
    float xB = hasB ? xp[32 + lane] : 0.f;

    for (int t = 0; t < Wn; t++) {
        float cxA = xA, cxB = xB;
        if (t + 1 < Wn) {
            xA = xp[(size_t)(t + 1) * 48 + lane];
            xB = hasB ? xp[(size_t)(t + 1) * 48 + 32 + lane] : 0.f;
        }
        // layer 0
        float dA = bhA0, dB = bhB0;
#pragma unroll
        for (int k = 0; k < 16; k++) {
            float hk = __shfl_sync(FULLMASK, h0, k);
            dA = fmaf(uA0[k], hk, dA);
            dB = fmaf(uB0[k], hk, dB);
        }
        float s  = sigm_(cxA + dA);
        float nv = tanh_(fmaf(s, dB, cxB));
        float zz = __shfl_sync(FULLMASK, s, 16 + (lane & 15));
        float h0n = fmaf(zz, h0 - nv, nv);
        h0 = hasB ? h0n : h0;
        // layer 1
        float xA1 = biA1, xB1 = biB1, dA1 = bhA1, dB1 = bhB1;
#pragma unroll
        for (int k = 0; k < 16; k++) {
            float hk  = __shfl_sync(FULLMASK, h0, k);
            xA1 = fmaf(wiA[k], hk, xA1);
            xB1 = fmaf(wiB[k], hk, xB1);
            float hk1 = __shfl_sync(FULLMASK, h1, k);
            dA1 = fmaf(uA1[k], hk1, dA1);
            dB1 = fmaf(uB1[k], hk1, dB1);
        }
        float s1  = sigm_(xA1 + dA1);
        float nv1 = tanh_(fmaf(s1, dB1, xB1));
        float z1  = __shfl_sync(FULLMASK, s1, 16 + (lane & 15));
        float h1n = fmaf(z1, h1 - nv1, nv1);
        h1 = hasB ? h1n : h1;
    }
    if (lane < 16) g_h1fin[b * 16 + lane] = h1;
}

// ============================================================================
// K5: decoder expert MLP (17->16->128) with BN over 64 rows. One block.
// ============================================================================
#define K5_SMEM_BYTES ((16384 + 1024 + 2176 + 128 + 1024 + 512 + 32 + 32) * 4)
__global__ void k_dec(
    const float* __restrict__ Remote,
    const float* __restrict__ w1, const float* __restrict__ b1,
    const float* __restrict__ w2, const float* __restrict__ b2,
    const float* __restrict__ gg, const float* __restrict__ bt,
    float* __restrict__ out)
{
    extern __shared__ float sm[];
    float* sw2   = sm;
    float* sb2   = sw2 + 16384;
    float* sw1   = sb2 + 1024;
    float* sb1   = sw1 + 2176;
    float* sh    = sb1 + 128;
    float* sro   = sh  + 1024;
    float* sstat = sro + 512;
    float* sgb   = sstat + 32;

    const int tid = threadIdx.x;
    for (int i = tid; i < 16384; i += 1024) sw2[i] = w2[i];
    if (tid < 1024) sb2[tid] = b2[tid];
    for (int i = tid; i < 2176; i += 1024) sw1[i] = w1[i];
    if (tid < 128) sb1[tid] = b1[tid];
    if (tid < 16) { sgb[tid] = gg[tid]; sgb[16 + tid] = bt[tid]; }
    __syncthreads();

    {   // phase 1
        const int b = tid >> 4, hh = tid & 15;
        float d[17];
#pragma unroll
        for (int k = 0; k < 16; k++) d[k] = g_h1fin[b * 16 + k];
        d[16] = Remote[((size_t)b * Wn + (Wn - 1)) * Fn + (An + TGTn)];
        float acc = 0.f;
#pragma unroll 1
        for (int e = 0; e < 8; e++) {
            float ro = g_Ro[((size_t)b * Wn + (Wn - 1)) * En + e];
            float pe = sb1[e * 16 + hh];
#pragma unroll
            for (int i = 0; i < 17; i++) pe = fmaf(d[i], sw1[e * 272 + i * 16 + hh], pe);
            acc = fmaf(ro, pe, acc);
        }
        sh[b * 16 + hh] = acc;
        if (hh < 8) sro[b * 8 + hh] = g_Ro[((size_t)b * Wn + (Wn - 1)) * En + hh];
    }
    __syncthreads();
    if (tid < 16) {   // BN stats (deterministic serial)
        float s = 0.f, q = 0.f;
        for (int b = 0; b < 64; b++) {
            float v = sh[b * 16 + tid];
            s += v; q = fmaf(v, v, q);
        }
        float mean = s * (1.0f / 64.0f);
        float var  = q * (1.0f / 64.0f) - mean * mean;
        sstat[tid] = mean;
        sstat[16 + tid] = rsqrtf(var + 1e-5f);
    }
    __syncthreads();
    {   // normalize + elu
        const int b = tid >> 4, hh = tid & 15;
        float v = sh[b * 16 + hh];
        v = fmaf(sgb[hh] * (v - sstat[hh]), sstat[16 + hh], sgb[16 + hh]);
        __syncthreads();
        sh[b * 16 + hh] = (v > 0.f) ? v : expm1f(v);
    }
    __syncthreads();
    {   // layer 2 -> output
        for (int k = 0; k < 8; k++) {
            int idx = tid + k * 1024;
            int b = idx >> 7, o = idx & 127;
            float acc = 0.f;
#pragma unroll 1
            for (int e = 0; e < 8; e++) {
                float pe = sb2[e * 128 + o];
#pragma unroll
                for (int h = 0; h < 16; h++)
                    pe = fmaf(sh[b * 16 + h], sw2[e * 2048 + h * 128 + o], pe);
                acc = fmaf(sro[b * 8 + e], pe, acc);
            }
            out[idx] = acc;
        }
    }
}

// ============================================================================
// Host launcher
// ============================================================================
extern "C" void kernel_launch(void* const* d_in, const int* in_sizes, int n_in,
                              void* d_out, int out_size)
{
    (void)n_in; (void)out_size;
    const float* P[30];
    for (int i = 0; i < 30; i++) P[i] = (const float*)d_in[i];

    const float *Local = P[0], *Remote = P[1];
    const float *gWih0 = P[2], *gWhh0 = P[3], *gbih0 = P[4], *gbhh0 = P[5];
    const float *gWih1 = P[6], *gWhh1 = P[7], *gbih1 = P[8], *gbhh1 = P[9];
    const float *aew1, *aeb1, *aew2, *aeb2, *aeg, *aebt;
    const float *mdw1, *mdb1, *mdw2, *mdb2, *mdg, *mdbt;
    const float *mWih0, *mWhh0, *mbih0, *mbhh0, *mWih1, *mWhh1, *mbih1, *mbhh1;

    if (in_sizes[10] == 16384) {   // reference-signature order
        aew1 = P[10]; aeb1 = P[11]; aew2 = P[12]; aeb2 = P[13]; aeg = P[14]; aebt = P[15];
        mdw1 = P[16]; mdb1 = P[17]; mdw2 = P[18]; mdb2 = P[19]; mdg = P[20]; mdbt = P[21];
        mWih0 = P[22]; mWhh0 = P[23]; mbih0 = P[24]; mbhh0 = P[25];
        mWih1 = P[26]; mWhh1 = P[27]; mbih1 = P[28]; mbhh1 = P[29];
    } else {                        // setup_inputs dict order
        mWih0 = P[10]; mWhh0 = P[11]; mbih0 = P[12]; mbhh0 = P[13];
        mWih1 = P[14]; mWhh1 = P[15]; mbih1 = P[16]; mbhh1 = P[17];
        aew1 = P[18]; aeb1 = P[19]; aew2 = P[20]; aeb2 = P[21]; aeg = P[22]; aebt = P[23];
        mdw1 = P[24]; mdb1 = P[25]; mdw2 = P[26]; mdb2 = P[27]; mdg = P[28]; mdbt = P[29];
    }

    cudaFuncSetAttribute(k_exp1, cudaFuncAttributeMaxDynamicSharedMemorySize, K2_SMEM_BYTES);
    cudaFuncSetAttribute(k_dec,  cudaFuncAttributeMaxDynamicSharedMemorySize, K5_SMEM_BYTES);

    k_gate<<<128, 32>>>(Local, Remote, gWih0, gWhh0, gbih0, gbhh0,
                        gWih1, gWhh1, gbih1, gbhh1);
    k_exp1<<<128, 256, K2_SMEM_BYTES>>>(Local, Remote, aew1, aeb1);
    k_bnstat<<<32, 256>>>();
    k_exp2<<<128, 64>>>(aew2, aeb2, aeg, aebt, mWih0, mbih0);
    k_mixer<<<64, 32>>>(mWhh0, mbhh0, mWih1, mbih1, mWhh1, mbhh1);
    k_dec<<<1, 1024, K5_SMEM_BYTES>>>(Remote, mdw1, mdb1, mdw2, mdb2, mdg, mdbt,
                                      (float*)d_out);
}